// round 2
// baseline (speedup 1.0000x reference)
#include <cuda_runtime.h>

// ---------------------------------------------------------------------------
// OctreeGnResBlock2: two fused gather-GEMM kernels, fp32 with packed f32x2 FMA.
//   K1: h = relu(GN_a(sum_k x[neigh[:,k]] @ Wa[k]))
//   K2: out = relu(GN_b(sum_k h[neigh[:,k]] @ Wb[k]) + GN_s(x @ W1))
// One thread = one node; 64-channel accumulator lives in registers as 32 f32x2
// pairs so GroupNorm (16 groups of 4 channels) is computed entirely in-register.
// NOTE: neigh is int32 (JAX default config downcasts the requested int64).
// ---------------------------------------------------------------------------

#define FMA2(d, a, b) asm("fma.rn.f32x2 %0, %1, %2, %0;" : "+l"(d) : "l"(a), "l"(b))

__device__ __forceinline__ unsigned long long pack2(float x) {
    unsigned long long r;
    asm("mov.b64 %0, {%1, %1};" : "=l"(r) : "f"(x));
    return r;
}
__device__ __forceinline__ float2 unpack2(unsigned long long v) {
    float2 r;
    asm("mov.b64 {%0, %1}, %2;" : "=f"(r.x), "=f"(r.y) : "l"(v));
    return r;
}

// Scratch for intermediate activation h [N, 64] (static: no allocs allowed).
__device__ float g_h[800000ULL * 64];

// ---------------------------------------------------------------------------
// Kernel 1: conv3x3a (gather GEMM, Cin=32 -> Cout=64) + GroupNorm + ReLU
// ---------------------------------------------------------------------------
__global__ void __launch_bounds__(256, 2) k_convA(
    const float* __restrict__ x, const int* __restrict__ neigh,
    const float* __restrict__ Wa, const float* __restrict__ gw,
    const float* __restrict__ gb, int n)
{
    __shared__ float sW[2][2048];   // double-buffered Wa[k] slice (32x64 fp32)
    const int tid  = threadIdx.x;
    const int node = blockIdx.x * 256 + tid;
    const bool active = node < n;

    // stage k = 0
    {
        const float4* src = (const float4*)Wa;
        float4* dst = (float4*)sW[0];
        dst[tid]       = src[tid];
        dst[tid + 256] = src[tid + 256];
    }

    unsigned long long acc[32];
#pragma unroll
    for (int i = 0; i < 32; ++i) acc[i] = 0ULL;   // (0.0f, 0.0f)

    const int* nrow = neigh + (long long)node * 27;

    for (int k = 0; k < 27; ++k) {
        __syncthreads();
        if (k + 1 < 27) {   // prefetch next W slice into the other buffer
            const float4* src = (const float4*)(Wa + (k + 1) * 2048);
            float4* dst = (float4*)sW[(k + 1) & 1];
            dst[tid]       = src[tid];
            dst[tid + 256] = src[tid + 256];
        }
        const long long idx = active ? (long long)nrow[k] : 0;
        const float4* xr4 = (const float4*)(x + idx * 32);
        float4 xr[8];
#pragma unroll
        for (int i = 0; i < 8; ++i) xr[i] = __ldg(xr4 + i);

        const unsigned long long* wb = (const unsigned long long*)sW[k & 1];
#pragma unroll
        for (int c4 = 0; c4 < 8; ++c4) {
            const float xs[4] = {xr[c4].x, xr[c4].y, xr[c4].z, xr[c4].w};
#pragma unroll
            for (int cc = 0; cc < 4; ++cc) {
                const unsigned long long xv2 = pack2(xs[cc]);
                const ulonglong2* wr =
                    (const ulonglong2*)(wb + (c4 * 4 + cc) * 32);
#pragma unroll
                for (int j = 0; j < 16; ++j) {
                    const ulonglong2 w = wr[j];
                    FMA2(acc[2 * j],     xv2, w.x);
                    FMA2(acc[2 * j + 1], xv2, w.y);
                }
            }
        }
    }

    if (active) {
        float4* out4 = (float4*)(g_h + (long long)node * 64);
#pragma unroll
        for (int g = 0; g < 16; ++g) {
            const float2 p0 = unpack2(acc[2 * g]);
            const float2 p1 = unpack2(acc[2 * g + 1]);
            const float mu = (p0.x + p0.y + p1.x + p1.y) * 0.25f;
            const float d0 = p0.x - mu, d1 = p0.y - mu;
            const float d2 = p1.x - mu, d3 = p1.y - mu;
            const float var = (d0 * d0 + d1 * d1 + d2 * d2 + d3 * d3) * 0.25f;
            const float rs = rsqrtf(var + 1e-5f);
            const int c = 4 * g;
            float4 o;
            o.x = fmaxf(fmaf(d0 * rs, __ldg(gw + c + 0), __ldg(gb + c + 0)), 0.f);
            o.y = fmaxf(fmaf(d1 * rs, __ldg(gw + c + 1), __ldg(gb + c + 1)), 0.f);
            o.z = fmaxf(fmaf(d2 * rs, __ldg(gw + c + 2), __ldg(gb + c + 2)), 0.f);
            o.w = fmaxf(fmaf(d3 * rs, __ldg(gw + c + 3), __ldg(gb + c + 3)), 0.f);
            out4[g] = o;
        }
    }
}

// ---------------------------------------------------------------------------
// Kernel 2: conv3x3b (gather GEMM, 64 -> 64) + GN_b, shortcut 1x1 + GN_s,
//           add + ReLU
// ---------------------------------------------------------------------------
__global__ void __launch_bounds__(256, 1) k_convB(
    const int* __restrict__ neigh,
    const float* __restrict__ Wb, const float* __restrict__ gbw,
    const float* __restrict__ gbb,
    const float* __restrict__ x, const float* __restrict__ W1,
    const float* __restrict__ gsw, const float* __restrict__ gsb,
    float* __restrict__ out, int n)
{
    __shared__ float sW[2][4096];   // double-buffered Wb[k] slice (64x64 fp32)
    __shared__ float sW1[2048];     // W1 (32x64 fp32), staged once
    const int tid  = threadIdx.x;
    const int node = blockIdx.x * 256 + tid;
    const bool active = node < n;

    {
        const float4* src = (const float4*)Wb;
        float4* dst = (float4*)sW[0];
#pragma unroll
        for (int i = 0; i < 4; ++i) dst[tid + i * 256] = src[tid + i * 256];
        const float4* s1 = (const float4*)W1;
        float4* d1 = (float4*)sW1;
        d1[tid]       = s1[tid];
        d1[tid + 256] = s1[tid + 256];
    }

    unsigned long long acc[32];
#pragma unroll
    for (int i = 0; i < 32; ++i) acc[i] = 0ULL;

    const int* nrow = neigh + (long long)node * 27;

    for (int k = 0; k < 27; ++k) {
        __syncthreads();
        if (k + 1 < 27) {
            const float4* src = (const float4*)(Wb + (k + 1) * 4096);
            float4* dst = (float4*)sW[(k + 1) & 1];
#pragma unroll
            for (int i = 0; i < 4; ++i) dst[tid + i * 256] = src[tid + i * 256];
        }
        const long long idx = active ? (long long)nrow[k] : 0;
        const float4* hr4 = (const float4*)(g_h + idx * 64);
        float4 xr[16];
#pragma unroll
        for (int i = 0; i < 16; ++i) xr[i] = __ldg(hr4 + i);

        const unsigned long long* wb64 = (const unsigned long long*)sW[k & 1];
#pragma unroll
        for (int c4 = 0; c4 < 16; ++c4) {
            const float xs[4] = {xr[c4].x, xr[c4].y, xr[c4].z, xr[c4].w};
#pragma unroll
            for (int cc = 0; cc < 4; ++cc) {
                const unsigned long long xv2 = pack2(xs[cc]);
                const ulonglong2* wr =
                    (const ulonglong2*)(wb64 + (c4 * 4 + cc) * 32);
#pragma unroll
                for (int j = 0; j < 16; ++j) {
                    const ulonglong2 w = wr[j];
                    FMA2(acc[2 * j],     xv2, w.x);
                    FMA2(acc[2 * j + 1], xv2, w.y);
                }
            }
        }
    }

    if (active) {
        // data row for the 1x1 shortcut
        const float4* xd4 = (const float4*)(x + (long long)node * 32);
        float4 xd[8];
#pragma unroll
        for (int i = 0; i < 8; ++i) xd[i] = __ldg(xd4 + i);

        float4* o4 = (float4*)(out + (long long)node * 64);
#pragma unroll
        for (int g = 0; g < 16; ++g) {
            // shortcut channels 4g..4g+3: sc = x @ W1[:, 4g:4g+4]
            float s0 = 0.f, s1 = 0.f, s2 = 0.f, s3 = 0.f;
#pragma unroll
            for (int c4 = 0; c4 < 8; ++c4) {
                const float xs[4] = {xd[c4].x, xd[c4].y, xd[c4].z, xd[c4].w};
#pragma unroll
                for (int cc = 0; cc < 4; ++cc) {
                    const float4 w =
                        *(const float4*)(sW1 + (c4 * 4 + cc) * 64 + 4 * g);
                    s0 = fmaf(xs[cc], w.x, s0);
                    s1 = fmaf(xs[cc], w.y, s1);
                    s2 = fmaf(xs[cc], w.z, s2);
                    s3 = fmaf(xs[cc], w.w, s3);
                }
            }
            // GN_s on shortcut group
            const float mus = (s0 + s1 + s2 + s3) * 0.25f;
            const float e0 = s0 - mus, e1 = s1 - mus, e2 = s2 - mus, e3 = s3 - mus;
            const float vars = (e0 * e0 + e1 * e1 + e2 * e2 + e3 * e3) * 0.25f;
            const float rss = rsqrtf(vars + 1e-5f);

            // GN_b on conv_b group
            const float2 p0 = unpack2(acc[2 * g]);
            const float2 p1 = unpack2(acc[2 * g + 1]);
            const float mub = (p0.x + p0.y + p1.x + p1.y) * 0.25f;
            const float d0 = p0.x - mub, d1 = p0.y - mub;
            const float d2 = p1.x - mub, d3 = p1.y - mub;
            const float varb = (d0 * d0 + d1 * d1 + d2 * d2 + d3 * d3) * 0.25f;
            const float rsb = rsqrtf(varb + 1e-5f);

            const int c = 4 * g;
            float4 o;
            o.x = fmaxf(fmaf(d0 * rsb, __ldg(gbw + c + 0), __ldg(gbb + c + 0)) +
                        fmaf(e0 * rss, __ldg(gsw + c + 0), __ldg(gsb + c + 0)), 0.f);
            o.y = fmaxf(fmaf(d1 * rsb, __ldg(gbw + c + 1), __ldg(gbb + c + 1)) +
                        fmaf(e1 * rss, __ldg(gsw + c + 1), __ldg(gsb + c + 1)), 0.f);
            o.z = fmaxf(fmaf(d2 * rsb, __ldg(gbw + c + 2), __ldg(gbb + c + 2)) +
                        fmaf(e2 * rss, __ldg(gsw + c + 2), __ldg(gsb + c + 2)), 0.f);
            o.w = fmaxf(fmaf(d3 * rsb, __ldg(gbw + c + 3), __ldg(gbb + c + 3)) +
                        fmaf(e3 * rss, __ldg(gsw + c + 3), __ldg(gsb + c + 3)), 0.f);
            o4[g] = o;
        }
    }
}

// ---------------------------------------------------------------------------
extern "C" void kernel_launch(void* const* d_in, const int* in_sizes, int n_in,
                              void* d_out, int out_size) {
    const float* data  = (const float*)d_in[0];
    const int*   neigh = (const int*)d_in[1];
    const float* Wa    = (const float*)d_in[2];
    const float* ga_w  = (const float*)d_in[3];
    const float* ga_b  = (const float*)d_in[4];
    const float* Wb    = (const float*)d_in[5];
    const float* gb_w  = (const float*)d_in[6];
    const float* gb_b  = (const float*)d_in[7];
    const float* W1    = (const float*)d_in[8];
    const float* gs_w  = (const float*)d_in[9];
    const float* gs_b  = (const float*)d_in[10];
    float* out = (float*)d_out;

    const int n = in_sizes[0] / 32;
    const int blocks = (n + 255) / 256;

    k_convA<<<blocks, 256>>>(data, neigh, Wa, ga_w, ga_b, n);
    k_convB<<<blocks, 256>>>(neigh, Wb, gb_w, gb_b, data, W1, gs_w, gs_b, out, n);
}

// round 4
// speedup vs baseline: 2.0384x; 2.0384x over previous
#include <cuda_runtime.h>
#include <cstdint>

// ===========================================================================
// OctreeGnResBlock2 via mma.sync tf32 (base PTX; tcgen05 unavailable: harness
// PTX targets compute_103 without the 'a' feature set).
//   prep : weights -> K-major [tap][cout][cin], tf32-rounded; x -> tf32-rounded
//   kA   : h  = relu(GN_a(sum_k gather(x) @ Wa[k]))            (27 taps, K=32)
//   kB   : out= relu(GN_b(sum_k gather(h) @ Wb[k]) + GN_s(x @ W1))
//          (shortcut = 28th tap, K=32, separate accumulators)
// CTA = 128 nodes / 256 thr; 8 warps tile 128x64 as 4(m32) x 2(n32).
// Smem rows padded to stride 68 (or 36) floats -> conflict-free LDS/STS.
// ===========================================================================

__device__ float g_h [800000ULL * 64];   // tf32-rounded activations
__device__ float g_xt[800000ULL * 32];   // tf32-rounded input
__device__ float g_Wat[27 * 64 * 32];    // [k][cout][cin] tf32-rounded
__device__ float g_Wbt[27 * 64 * 64];
__device__ float g_W1t[64 * 32];

__device__ __forceinline__ float totf32(float f) {
    uint32_t u;
    asm("cvt.rna.tf32.f32 %0, %1;" : "=r"(u) : "f"(f));
    return __uint_as_float(u);
}

#define MMA(c, a, b0, b1)                                                    \
    asm volatile(                                                            \
        "mma.sync.aligned.m16n8k8.row.col.f32.tf32.tf32.f32 "                \
        "{%0,%1,%2,%3},{%4,%5,%6,%7},{%8,%9},{%0,%1,%2,%3};"                 \
        : "+f"((c)[0]), "+f"((c)[1]), "+f"((c)[2]), "+f"((c)[3])             \
        : "r"((a)[0]), "r"((a)[1]), "r"((a)[2]), "r"((a)[3]),                \
          "r"(b0), "r"(b1))

// one gathered tap: A[128 x 8*S] @ B[64 x 8*S]^T accumulated into c[2][4][4]
template <int STRIDE, int S>
__device__ __forceinline__ void tap_mma(const float* __restrict__ sA,
                                        const float* __restrict__ sW,
                                        float c[2][4][4], int lid, int wid) {
    const int g = lid >> 2, t = lid & 3;
    const float* pa = sA + ((wid & 3) * 32 + g) * STRIDE + t;
    const float* pb = sW + ((wid >> 2) * 32 + g) * STRIDE + t;
#pragma unroll
    for (int s = 0; s < S; ++s) {
        uint32_t a[2][4];
#pragma unroll
        for (int m = 0; m < 2; ++m) {
            const float* p = pa + m * 16 * STRIDE + s * 8;
            a[m][0] = __float_as_uint(p[0]);
            a[m][1] = __float_as_uint(p[8 * STRIDE]);
            a[m][2] = __float_as_uint(p[4]);
            a[m][3] = __float_as_uint(p[8 * STRIDE + 4]);
        }
#pragma unroll
        for (int nn = 0; nn < 4; ++nn) {
            const float* q = pb + nn * 8 * STRIDE + s * 8;
            const uint32_t b0 = __float_as_uint(q[0]);
            const uint32_t b1 = __float_as_uint(q[4]);
            MMA(c[0][nn], a[0], b0, b1);
            MMA(c[1][nn], a[1], b0, b1);
        }
    }
}

// ---------------- prep ----------------
__global__ void k_prepW(const float* __restrict__ Wa,
                        const float* __restrict__ Wb,
                        const float* __restrict__ W1) {
    const int t = blockIdx.x * 256 + threadIdx.x;
    if (t < 27 * 64 * 32) {
        const int k = t / 2048, o = (t % 2048) / 32, i = t % 32;
        g_Wat[t] = totf32(Wa[k * 2048 + i * 64 + o]);
    }
    if (t < 27 * 64 * 64) {
        const int k = t / 4096, o = (t % 4096) / 64, i = t % 64;
        g_Wbt[t] = totf32(Wb[k * 4096 + i * 64 + o]);
    }
    if (t < 2048) {
        const int o = t / 32, i = t % 32;
        g_W1t[t] = totf32(W1[i * 64 + o]);
    }
}
__global__ void k_prepX(const float* __restrict__ x, long long n32) {
    for (long long i = blockIdx.x * 256LL + threadIdx.x; i < n32;
         i += (long long)gridDim.x * 256)
        g_xt[i] = totf32(x[i]);
}

// ---------------- kernel A ----------------
// smem: snei 13824B @0, sA 128x36 f @13824 (18432B), sW 64x36 f @32256 (9216B)
static constexpr int A_SM = 41472;

__global__ void __launch_bounds__(256, 2) kA(
    const int* __restrict__ neigh, const float* __restrict__ gw,
    const float* __restrict__ gb, int n)
{
    extern __shared__ char smem[];
    int*   snei = (int*)smem;
    float* sA   = (float*)(smem + 13824);
    float* sW   = (float*)(smem + 32256);
    const int tid = threadIdx.x, wid = tid >> 5, lid = tid & 31;
    const int tile = blockIdx.x;
    const int rows = min(128, n - tile * 128);

    for (int i = tid; i < rows * 27; i += 256)
        snei[i] = neigh[(long long)tile * 128 * 27 + i];

    float c[2][4][4];
#pragma unroll
    for (int m = 0; m < 2; ++m)
#pragma unroll
        for (int nn = 0; nn < 4; ++nn)
#pragma unroll
            for (int j = 0; j < 4; ++j) c[m][nn][j] = 0.f;

    for (int k = 0; k < 27; ++k) {
        __syncthreads();
#pragma unroll
        for (int j = 0; j < 4; ++j) {           // A: 128 rows x 8 float4
            const int lin = tid + j * 256, row = lin >> 3, seg = lin & 7;
            const long long idx = (row < rows) ? (long long)snei[row * 27 + k] : 0;
            *(float4*)(sA + row * 36 + seg * 4) =
                __ldg((const float4*)(g_xt + idx * 32) + seg);
        }
#pragma unroll
        for (int j = 0; j < 2; ++j) {           // W: 64 rows x 8 float4
            const int lin = tid + j * 256, row = lin >> 3, seg = lin & 7;
            *(float4*)(sW + row * 36 + seg * 4) =
                __ldg((const float4*)(g_Wat + k * 2048) + lin);
        }
        __syncthreads();
        tap_mma<36, 4>(sA, sW, c, lid, wid);
    }

    // epilogue: GroupNorm(groups of 4) + ReLU, tf32-round, store to g_h
    const int g = lid >> 2, t = lid & 3;
    const int mbase = (wid & 3) * 32, nbase = (wid >> 2) * 32;
#pragma unroll
    for (int m = 0; m < 2; ++m)
#pragma unroll
        for (int h = 0; h < 2; ++h) {
            const int row = mbase + m * 16 + g + h * 8;
#pragma unroll
            for (int nn = 0; nn < 4; ++nn) {
                const float v0 = c[m][nn][h * 2], v1 = c[m][nn][h * 2 + 1];
                float s = v0 + v1;
                s += __shfl_xor_sync(0xffffffffu, s, 1);
                const float mu = s * 0.25f;
                const float d0 = v0 - mu, d1 = v1 - mu;
                float q = d0 * d0 + d1 * d1;
                q += __shfl_xor_sync(0xffffffffu, q, 1);
                const float rs = rsqrtf(q * 0.25f + 1e-5f);
                const int col = nbase + nn * 8 + t * 2;
                if (row < rows) {
                    float2 o;
                    o.x = totf32(fmaxf(fmaf(d0 * rs, __ldg(gw + col),
                                            __ldg(gb + col)), 0.f));
                    o.y = totf32(fmaxf(fmaf(d1 * rs, __ldg(gw + col + 1),
                                            __ldg(gb + col + 1)), 0.f));
                    *(float2*)(g_h + ((long long)tile * 128 + row) * 64 + col) = o;
                }
            }
        }
}

// ---------------- kernel B ----------------
// smem: snei 13824B @0, sA 128x68 f @13824 (34816B), sW 64x68 f @48640 (17408B)
static constexpr int B_SM = 66048;

__global__ void __launch_bounds__(256, 2) kB(
    const int* __restrict__ neigh,
    const float* __restrict__ gbw, const float* __restrict__ gbb,
    const float* __restrict__ gsw, const float* __restrict__ gsb,
    float* __restrict__ out, int n)
{
    extern __shared__ char smem[];
    int*   snei = (int*)smem;
    float* sA   = (float*)(smem + 13824);
    float* sW   = (float*)(smem + 48640);
    const int tid = threadIdx.x, wid = tid >> 5, lid = tid & 31;
    const int tile = blockIdx.x;
    const int rows = min(128, n - tile * 128);

    for (int i = tid; i < rows * 27; i += 256)
        snei[i] = neigh[(long long)tile * 128 * 27 + i];

    float c[2][4][4], csc[2][4][4];
#pragma unroll
    for (int m = 0; m < 2; ++m)
#pragma unroll
        for (int nn = 0; nn < 4; ++nn)
#pragma unroll
            for (int j = 0; j < 4; ++j) { c[m][nn][j] = 0.f; csc[m][nn][j] = 0.f; }

    for (int k = 0; k < 27; ++k) {
        __syncthreads();
#pragma unroll
        for (int j = 0; j < 8; ++j) {           // A: 128 rows x 16 float4 (h)
            const int lin = tid + j * 256, row = lin >> 4, seg = lin & 15;
            const long long idx = (row < rows) ? (long long)snei[row * 27 + k] : 0;
            *(float4*)(sA + row * 68 + seg * 4) =
                __ldg((const float4*)(g_h + idx * 64) + seg);
        }
#pragma unroll
        for (int j = 0; j < 4; ++j) {           // W: 64 rows x 16 float4
            const int lin = tid + j * 256, row = lin >> 4, seg = lin & 15;
            *(float4*)(sW + row * 68 + seg * 4) =
                __ldg((const float4*)(g_Wbt + k * 4096) + lin);
        }
        __syncthreads();
        tap_mma<68, 8>(sA, sW, c, lid, wid);
    }

    // shortcut tap: A = x (K=32), B = W1t
    __syncthreads();
#pragma unroll
    for (int j = 0; j < 4; ++j) {
        const int lin = tid + j * 256, row = lin >> 3, seg = lin & 7;
        const long long node = (long long)tile * 128 + ((row < rows) ? row : 0);
        *(float4*)(sA + row * 68 + seg * 4) =
            __ldg((const float4*)(g_xt + node * 32) + seg);
    }
#pragma unroll
    for (int j = 0; j < 2; ++j) {
        const int lin = tid + j * 256, row = lin >> 3, seg = lin & 7;
        *(float4*)(sW + row * 68 + seg * 4) = __ldg((const float4*)g_W1t + lin);
    }
    __syncthreads();
    tap_mma<68, 4>(sA, sW, csc, lid, wid);

    // epilogue: GN_b(c) + GN_s(csc), add, ReLU, store
    const int g = lid >> 2, t = lid & 3;
    const int mbase = (wid & 3) * 32, nbase = (wid >> 2) * 32;
#pragma unroll
    for (int m = 0; m < 2; ++m)
#pragma unroll
        for (int h = 0; h < 2; ++h) {
            const int row = mbase + m * 16 + g + h * 8;
#pragma unroll
            for (int nn = 0; nn < 4; ++nn) {
                // conv branch stats
                const float v0 = c[m][nn][h * 2], v1 = c[m][nn][h * 2 + 1];
                float s = v0 + v1;
                s += __shfl_xor_sync(0xffffffffu, s, 1);
                const float mub = s * 0.25f;
                const float d0 = v0 - mub, d1 = v1 - mub;
                float q = d0 * d0 + d1 * d1;
                q += __shfl_xor_sync(0xffffffffu, q, 1);
                const float rb = rsqrtf(q * 0.25f + 1e-5f);
                // shortcut branch stats
                const float w0 = csc[m][nn][h * 2], w1 = csc[m][nn][h * 2 + 1];
                float s2 = w0 + w1;
                s2 += __shfl_xor_sync(0xffffffffu, s2, 1);
                const float mus = s2 * 0.25f;
                const float e0 = w0 - mus, e1 = w1 - mus;
                float q2 = e0 * e0 + e1 * e1;
                q2 += __shfl_xor_sync(0xffffffffu, q2, 1);
                const float rs = rsqrtf(q2 * 0.25f + 1e-5f);

                const int col = nbase + nn * 8 + t * 2;
                if (row < rows) {
                    float2 o;
                    o.x = fmaxf(fmaf(d0 * rb, __ldg(gbw + col), __ldg(gbb + col)) +
                                fmaf(e0 * rs, __ldg(gsw + col), __ldg(gsb + col)),
                                0.f);
                    o.y = fmaxf(fmaf(d1 * rb, __ldg(gbw + col + 1), __ldg(gbb + col + 1)) +
                                fmaf(e1 * rs, __ldg(gsw + col + 1), __ldg(gsb + col + 1)),
                                0.f);
                    *(float2*)(out + ((long long)tile * 128 + row) * 64 + col) = o;
                }
            }
        }
}

// ---------------------------------------------------------------------------
extern "C" void kernel_launch(void* const* d_in, const int* in_sizes, int n_in,
                              void* d_out, int out_size) {
    const float* data  = (const float*)d_in[0];
    const int*   neigh = (const int*)d_in[1];
    const float* Wa    = (const float*)d_in[2];
    const float* ga_w  = (const float*)d_in[3];
    const float* ga_b  = (const float*)d_in[4];
    const float* Wb    = (const float*)d_in[5];
    const float* gb_w  = (const float*)d_in[6];
    const float* gb_b  = (const float*)d_in[7];
    const float* W1    = (const float*)d_in[8];
    const float* gs_w  = (const float*)d_in[9];
    const float* gs_b  = (const float*)d_in[10];
    float* out = (float*)d_out;

    const int n = in_sizes[0] / 32;
    const int tiles = (n + 127) / 128;

    static bool attr_set = false;
    if (!attr_set) {
        cudaFuncSetAttribute(kA, cudaFuncAttributeMaxDynamicSharedMemorySize, A_SM);
        cudaFuncSetAttribute(kB, cudaFuncAttributeMaxDynamicSharedMemorySize, B_SM);
        attr_set = true;
    }

    k_prepW<<<(27 * 64 * 64 + 255) / 256, 256>>>(Wa, Wb, W1);
    k_prepX<<<2048, 256>>>(data, (long long)n * 32);
    kA<<<tiles, 256, A_SM>>>(neigh, ga_w, ga_b, n);
    kB<<<tiles, 256, B_SM>>>(neigh, gb_w, gb_b, gs_w, gs_b, out, n);
}

// round 5
// speedup vs baseline: 3.7927x; 1.8607x over previous
#include <cuda_runtime.h>
#include <cstdint>

// ===========================================================================
// OctreeGnResBlock2 via mma.sync tf32 + cp.async double-buffered tap pipeline.
//   prep : weights -> K-major [tap][cout][cin] tf32-rounded; x -> tf32-rounded
//   kA   : h  = relu(GN_a(sum_k gather(x) @ Wa[k]))            (27 taps, K=32)
//   kB   : out= relu(GN_b(sum_k gather(h) @ Wb[k]) + GN_s(x @ W1))
//          (shortcut = pipelined 28th tap, separate accumulators)
// CTA = 128 nodes / 256 thr; 8 warps tile 128x64 as 4(m32) x 2(n32).
// Smem tiles use XOR-swizzled 16B blocks (conflict-free, zero padding) so two
// stages x 2 CTAs fit; tap k+1 gathers stream under tap k's MMAs.
// ===========================================================================

__device__ float g_h [800000ULL * 64];   // tf32-rounded activations
__device__ float g_xt[800000ULL * 32];   // tf32-rounded input
__device__ float g_Wat[27 * 64 * 32];    // [k][cout][cin] tf32-rounded
__device__ float g_Wbt[27 * 64 * 64];
__device__ float g_W1t[64 * 32];

__device__ __forceinline__ float totf32(float f) {
    uint32_t u;
    asm("cvt.rna.tf32.f32 %0, %1;" : "=r"(u) : "f"(f));
    return __uint_as_float(u);
}
__device__ __forceinline__ uint32_t s2u(const void* p) {
    uint32_t a;
    asm("{ .reg .u64 t; cvta.to.shared.u64 t, %1; cvt.u32.u64 %0, t; }"
        : "=r"(a) : "l"(p));
    return a;
}
__device__ __forceinline__ void cpa16(uint32_t d, const void* s) {
    asm volatile("cp.async.cg.shared.global [%0], [%1], 16;" :: "r"(d), "l"(s));
}
#define CPA_COMMIT() asm volatile("cp.async.commit_group;" ::: "memory")
#define CPA_WAIT0()  asm volatile("cp.async.wait_group 0;"  ::: "memory")

// 16B-block XOR swizzle within a row (row&7 pattern)
__device__ __forceinline__ int swz(int row, int blk) {
    return (blk & 8) | ((blk & 7) ^ (row & 7));
}

#define MMA(c, a, b0, b1)                                                    \
    asm volatile(                                                            \
        "mma.sync.aligned.m16n8k8.row.col.f32.tf32.tf32.f32 "                \
        "{%0,%1,%2,%3},{%4,%5,%6,%7},{%8,%9},{%0,%1,%2,%3};"                 \
        : "+f"((c)[0]), "+f"((c)[1]), "+f"((c)[2]), "+f"((c)[3])             \
        : "r"((a)[0]), "r"((a)[1]), "r"((a)[2]), "r"((a)[3]),                \
          "r"(b0), "r"(b1))

// one tap: A[128 x 8S] @ B[64 x 8S]^T into c[2][4][4]; NBLK = 16B blocks/row
template <int NBLK, int S>
__device__ __forceinline__ void tap_mma(const float* __restrict__ sA,
                                        const float* __restrict__ sW,
                                        float c[2][4][4], int lid, int wid) {
    const int g = lid >> 2, t = lid & 3;
    const int RS = NBLK * 4;                       // floats per row
    const float* pa = sA + ((wid & 3) * 32 + g) * RS + t;
    const float* pb = sW + ((wid >> 2) * 32 + g) * RS + t;
#pragma unroll
    for (int s = 0; s < S; ++s) {
        const int o0 = (((2 * s) & 8) | (((2 * s) & 7) ^ g)) * 4;
        const int o1 = (((2 * s + 1) & 8) | (((2 * s + 1) & 7) ^ g)) * 4;
        uint32_t a[2][4];
#pragma unroll
        for (int m = 0; m < 2; ++m) {
            const float* p = pa + m * 16 * RS;
            a[m][0] = __float_as_uint(p[o0]);
            a[m][1] = __float_as_uint(p[8 * RS + o0]);
            a[m][2] = __float_as_uint(p[o1]);
            a[m][3] = __float_as_uint(p[8 * RS + o1]);
        }
#pragma unroll
        for (int nn = 0; nn < 4; ++nn) {
            const float* q = pb + nn * 8 * RS;
            const uint32_t b0 = __float_as_uint(q[o0]);
            const uint32_t b1 = __float_as_uint(q[o1]);
            MMA(c[0][nn], a[0], b0, b1);
            MMA(c[1][nn], a[1], b0, b1);
        }
    }
}

// ---------------- prep ----------------
__global__ void k_prepW(const float* __restrict__ Wa,
                        const float* __restrict__ Wb,
                        const float* __restrict__ W1) {
    const int t = blockIdx.x * 256 + threadIdx.x;
    if (t < 27 * 64 * 32) {
        const int k = t / 2048, o = (t % 2048) / 32, i = t % 32;
        g_Wat[t] = totf32(Wa[k * 2048 + i * 64 + o]);
    }
    if (t < 27 * 64 * 64) {
        const int k = t / 4096, o = (t % 4096) / 64, i = t % 64;
        g_Wbt[t] = totf32(Wb[k * 4096 + i * 64 + o]);
    }
    if (t < 2048) {
        const int o = t / 32, i = t % 32;
        g_W1t[t] = totf32(W1[i * 64 + o]);
    }
}
__global__ void k_prepX(const float* __restrict__ x, long long n32) {
    for (long long i = blockIdx.x * 256LL + threadIdx.x; i < n32;
         i += (long long)gridDim.x * 256)
        g_xt[i] = totf32(x[i]);
}

// ---------------- kernel A ----------------
// smem: snei 13824 | A0 16384 | W0 8192 | A1 16384 | W1 8192  = 62976
static constexpr int A_SM = 62976;

__global__ void __launch_bounds__(256, 2) kA(
    const int* __restrict__ neigh, const float* __restrict__ gw,
    const float* __restrict__ gb, int n)
{
    extern __shared__ char smem[];
    int* snei = (int*)smem;
    const uint32_t sbase = s2u(smem);
    const uint32_t aU[2] = {sbase + 13824u, sbase + 38400u};
    const uint32_t wU[2] = {sbase + 30208u, sbase + 54784u};
    const float* aF[2] = {(const float*)(smem + 13824), (const float*)(smem + 38400)};
    const float* wF[2] = {(const float*)(smem + 30208), (const float*)(smem + 54784)};

    const int tid = threadIdx.x, wid = tid >> 5, lid = tid & 31;
    const int tile = blockIdx.x;
    const int rows = min(128, n - tile * 128);

    for (int i = tid; i < rows * 27; i += 256)
        snei[i] = neigh[(long long)tile * 128 * 27 + i];
    __syncthreads();

    float c[2][4][4];
#pragma unroll
    for (int m = 0; m < 2; ++m)
#pragma unroll
        for (int nn = 0; nn < 4; ++nn)
#pragma unroll
            for (int j = 0; j < 4; ++j) c[m][nn][j] = 0.f;

    auto stage = [&](int k) {
        const int buf = k & 1;
#pragma unroll
        for (int j = 0; j < 4; ++j) {            // A: 128 rows x 8 blks
            const int lin = tid + j * 256, row = lin >> 3, seg = lin & 7;
            const long long idx = (row < rows) ? (long long)snei[row * 27 + k] : 0;
            cpa16(aU[buf] + (row * 8 + swz(row, seg)) * 16,
                  g_xt + idx * 32 + seg * 4);
        }
#pragma unroll
        for (int j = 0; j < 2; ++j) {            // W: 64 rows x 8 blks
            const int lin = tid + j * 256, row = lin >> 3, seg = lin & 7;
            cpa16(wU[buf] + (row * 8 + swz(row, seg)) * 16,
                  g_Wat + k * 2048 + row * 32 + seg * 4);
        }
        CPA_COMMIT();
    };

    stage(0);
    for (int k = 0; k < 27; ++k) {
        CPA_WAIT0();
        __syncthreads();                // buf k visible; buf k-1 reads done
        if (k + 1 < 27) stage(k + 1);   // streams under this tap's MMAs
        tap_mma<8, 4>(aF[k & 1], wF[k & 1], c, lid, wid);
    }

    // epilogue: GN_a (groups of 4) + ReLU, tf32-round, store h
    const int g = lid >> 2, t = lid & 3;
    const int mbase = (wid & 3) * 32, nbase = (wid >> 2) * 32;
#pragma unroll
    for (int m = 0; m < 2; ++m)
#pragma unroll
        for (int h = 0; h < 2; ++h) {
            const int row = mbase + m * 16 + g + h * 8;
#pragma unroll
            for (int nn = 0; nn < 4; ++nn) {
                const float v0 = c[m][nn][h * 2], v1 = c[m][nn][h * 2 + 1];
                float s = v0 + v1;
                s += __shfl_xor_sync(0xffffffffu, s, 1);
                const float mu = s * 0.25f;
                const float d0 = v0 - mu, d1 = v1 - mu;
                float q = d0 * d0 + d1 * d1;
                q += __shfl_xor_sync(0xffffffffu, q, 1);
                const float rs = rsqrtf(q * 0.25f + 1e-5f);
                const int col = nbase + nn * 8 + t * 2;
                if (row < rows) {
                    float2 o;
                    o.x = totf32(fmaxf(fmaf(d0 * rs, __ldg(gw + col),
                                            __ldg(gb + col)), 0.f));
                    o.y = totf32(fmaxf(fmaf(d1 * rs, __ldg(gw + col + 1),
                                            __ldg(gb + col + 1)), 0.f));
                    *(float2*)(g_h + ((long long)tile * 128 + row) * 64 + col) = o;
                }
            }
        }
}

// ---------------- kernel B ----------------
// smem: snei 13824 | A0 32768 | W0 16384 | A1 32768 | W1 16384 = 112128
static constexpr int B_SM = 112128;

__global__ void __launch_bounds__(256, 2) kB(
    const int* __restrict__ neigh,
    const float* __restrict__ gbw, const float* __restrict__ gbb,
    const float* __restrict__ gsw, const float* __restrict__ gsb,
    float* __restrict__ out, int n)
{
    extern __shared__ char smem[];
    int* snei = (int*)smem;
    const uint32_t sbase = s2u(smem);
    const uint32_t aU[2] = {sbase + 13824u, sbase + 62976u};
    const uint32_t wU[2] = {sbase + 46592u, sbase + 95744u};
    const float* aF[2] = {(const float*)(smem + 13824), (const float*)(smem + 62976)};
    const float* wF[2] = {(const float*)(smem + 46592), (const float*)(smem + 95744)};

    const int tid = threadIdx.x, wid = tid >> 5, lid = tid & 31;
    const int tile = blockIdx.x;
    const int rows = min(128, n - tile * 128);

    for (int i = tid; i < rows * 27; i += 256)
        snei[i] = neigh[(long long)tile * 128 * 27 + i];
    __syncthreads();

    float c[2][4][4], csc[2][4][4];
#pragma unroll
    for (int m = 0; m < 2; ++m)
#pragma unroll
        for (int nn = 0; nn < 4; ++nn)
#pragma unroll
            for (int j = 0; j < 4; ++j) { c[m][nn][j] = 0.f; csc[m][nn][j] = 0.f; }

    auto stage = [&](int k) {
        const int buf = k & 1;
        if (k < 27) {
#pragma unroll
            for (int j = 0; j < 8; ++j) {        // A: 128 rows x 16 blks (h)
                const int lin = tid + j * 256, row = lin >> 4, seg = lin & 15;
                const long long idx =
                    (row < rows) ? (long long)snei[row * 27 + k] : 0;
                cpa16(aU[buf] + (row * 16 + swz(row, seg)) * 16,
                      g_h + idx * 64 + seg * 4);
            }
#pragma unroll
            for (int j = 0; j < 4; ++j) {        // W: 64 rows x 16 blks
                const int lin = tid + j * 256, row = lin >> 4, seg = lin & 15;
                cpa16(wU[buf] + (row * 16 + swz(row, seg)) * 16,
                      g_Wbt + k * 4096 + row * 64 + seg * 4);
            }
        } else {                                  // shortcut tap: x @ W1t
#pragma unroll
            for (int j = 0; j < 4; ++j) {        // A: 128 rows x 8 blks (x)
                const int lin = tid + j * 256, row = lin >> 3, seg = lin & 7;
                const long long node =
                    (long long)tile * 128 + ((row < rows) ? row : 0);
                cpa16(aU[buf] + (row * 16 + swz(row, seg)) * 16,
                      g_xt + node * 32 + seg * 4);
            }
#pragma unroll
            for (int j = 0; j < 2; ++j) {        // W: 64 rows x 8 blks
                const int lin = tid + j * 256, row = lin >> 3, seg = lin & 7;
                cpa16(wU[buf] + (row * 16 + swz(row, seg)) * 16,
                      g_W1t + row * 32 + seg * 4);
            }
        }
        CPA_COMMIT();
    };

    stage(0);
    for (int k = 0; k < 28; ++k) {
        CPA_WAIT0();
        __syncthreads();
        if (k + 1 < 28) stage(k + 1);
        if (k < 27) tap_mma<16, 8>(aF[k & 1], wF[k & 1], c, lid, wid);
        else        tap_mma<16, 4>(aF[k & 1], wF[k & 1], csc, lid, wid);
    }

    // epilogue: GN_b(c) + GN_s(csc), add, ReLU
    const int g = lid >> 2, t = lid & 3;
    const int mbase = (wid & 3) * 32, nbase = (wid >> 2) * 32;
#pragma unroll
    for (int m = 0; m < 2; ++m)
#pragma unroll
        for (int h = 0; h < 2; ++h) {
            const int row = mbase + m * 16 + g + h * 8;
#pragma unroll
            for (int nn = 0; nn < 4; ++nn) {
                const float v0 = c[m][nn][h * 2], v1 = c[m][nn][h * 2 + 1];
                float s = v0 + v1;
                s += __shfl_xor_sync(0xffffffffu, s, 1);
                const float mub = s * 0.25f;
                const float d0 = v0 - mub, d1 = v1 - mub;
                float q = d0 * d0 + d1 * d1;
                q += __shfl_xor_sync(0xffffffffu, q, 1);
                const float rb = rsqrtf(q * 0.25f + 1e-5f);

                const float w0 = csc[m][nn][h * 2], w1 = csc[m][nn][h * 2 + 1];
                float s2 = w0 + w1;
                s2 += __shfl_xor_sync(0xffffffffu, s2, 1);
                const float mus = s2 * 0.25f;
                const float e0 = w0 - mus, e1 = w1 - mus;
                float q2 = e0 * e0 + e1 * e1;
                q2 += __shfl_xor_sync(0xffffffffu, q2, 1);
                const float rs = rsqrtf(q2 * 0.25f + 1e-5f);

                const int col = nbase + nn * 8 + t * 2;
                if (row < rows) {
                    float2 o;
                    o.x = fmaxf(fmaf(d0 * rb, __ldg(gbw + col), __ldg(gbb + col)) +
                                fmaf(e0 * rs, __ldg(gsw + col), __ldg(gsb + col)),
                                0.f);
                    o.y = fmaxf(fmaf(d1 * rb, __ldg(gbw + col + 1), __ldg(gbb + col + 1)) +
                                fmaf(e1 * rs, __ldg(gsw + col + 1), __ldg(gsb + col + 1)),
                                0.f);
                    *(float2*)(out + ((long long)tile * 128 + row) * 64 + col) = o;
                }
            }
        }
}

// ---------------------------------------------------------------------------
extern "C" void kernel_launch(void* const* d_in, const int* in_sizes, int n_in,
                              void* d_out, int out_size) {
    const float* data  = (const float*)d_in[0];
    const int*   neigh = (const int*)d_in[1];
    const float* Wa    = (const float*)d_in[2];
    const float* ga_w  = (const float*)d_in[3];
    const float* ga_b  = (const float*)d_in[4];
    const float* Wb    = (const float*)d_in[5];
    const float* gb_w  = (const float*)d_in[6];
    const float* gb_b  = (const float*)d_in[7];
    const float* W1    = (const float*)d_in[8];
    const float* gs_w  = (const float*)d_in[9];
    const float* gs_b  = (const float*)d_in[10];
    float* out = (float*)d_out;

    const int n = in_sizes[0] / 32;
    const int tiles = (n + 127) / 128;

    cudaFuncSetAttribute(kA, cudaFuncAttributeMaxDynamicSharedMemorySize, A_SM);
    cudaFuncSetAttribute(kB, cudaFuncAttributeMaxDynamicSharedMemorySize, B_SM);

    k_prepW<<<(27 * 64 * 64 + 255) / 256, 256>>>(Wa, Wb, W1);
    k_prepX<<<2048, 256>>>(data, (long long)n * 32);
    kA<<<tiles, 256, A_SM>>>(neigh, ga_w, ga_b, n);
    kB<<<tiles, 256, B_SM>>>(neigh, gb_w, gb_b, gs_w, gs_b, out, n);
}